// round 6
// baseline (speedup 1.0000x reference)
#include <cuda_runtime.h>
#include <cstdint>
#include <math.h>

#define NN 100000
#define CC 128
#define HH 256
#define ADIM 1000
#define EE_MAX 1700000

// ---------------- device scratch (no allocations allowed) ----------------
static __device__ float g_h[(size_t)NN * CC];     // conv linear output
static __device__ float g_r[(size_t)NN * CC];     // aggregated / residual
static __device__ float g_dinv[NN];               // rsqrt(deg) incl self-loop
static __device__ int   g_cnt[NN];                // in-degree counts
static __device__ int   g_cur[NN];                // bucket cursors
static __device__ int   g_off[NN + 1];            // CSR offsets
static __device__ int   g_bsum[512];              // block sums for scan
static __device__ int   g_csr[EE_MAX];            // CSR src lists
static __device__ float g_h1[(size_t)NN * HH];
static __device__ float g_h2[(size_t)NN * HH];
static __device__ float g_conc[NN];
static __device__ float g_lg[NN];                 // log-gamma samples
static __device__ int   g_mode;                   // detected RNG convention

// ---------------- threefry2x32 block (JAX-exact) ----------------
__device__ __forceinline__ void tf2x32(uint32_t k0, uint32_t k1,
                                       uint32_t& x0, uint32_t& x1) {
  uint32_t k2 = k0 ^ k1 ^ 0x1BD11BDAu;
  x0 += k0; x1 += k1;
#define TF_R(r) { x0 += x1; x1 = (x1 << (r)) | (x1 >> (32 - (r))); x1 ^= x0; }
  TF_R(13) TF_R(15) TF_R(26) TF_R(6)
  x0 += k1; x1 += k2 + 1u;
  TF_R(17) TF_R(29) TF_R(16) TF_R(24)
  x0 += k2; x1 += k0 + 2u;
  TF_R(13) TF_R(15) TF_R(26) TF_R(6)
  x0 += k0; x1 += k1 + 3u;
  TF_R(17) TF_R(29) TF_R(16) TF_R(24)
  x0 += k1; x1 += k2 + 4u;
  TF_R(13) TF_R(15) TF_R(26) TF_R(6)
  x0 += k2; x1 += k0 + 5u;
#undef TF_R
}

// original-mode threefry_2x32 over iota(2n): out[m] for m in [0,2n)
__device__ __forceinline__ uint32_t orig_out(uint32_t k0, uint32_t k1,
                                             uint32_t m, uint32_t n) {
  uint32_t o0, o1;
  if (m < n) { o0 = m;     o1 = n + m; }
  else       { o0 = m - n; o1 = m;     }
  tf2x32(k0, k1, o0, o1);
  return (m < n) ? o0 : o1;
}

// RNG conventions: 0 = foldlike split + xor bits, 1 = foldlike + hi word,
//                  2 = foldlike + lo word,        3 = original split (+pad-block bits)
__device__ __forceinline__ uint32_t bits32(int mode, uint32_t k0, uint32_t k1) {
  uint32_t a = 0u, b = 0u;
  tf2x32(k0, k1, a, b);
  if (mode == 0) return a ^ b;
  if (mode == 2) return b;
  return a;                     // modes 1 and 3 (orig scalar: o0 of block(0,0))
}

// split into 2 children
__device__ __forceinline__ void split2(int mode, uint32_t k0, uint32_t k1,
                                       uint32_t& a0, uint32_t& a1,
                                       uint32_t& b0, uint32_t& b1) {
  if (mode < 3) {
    a0 = 0u; a1 = 0u; tf2x32(k0, k1, a0, a1);
    b0 = 0u; b1 = 1u; tf2x32(k0, k1, b0, b1);
  } else {
    a0 = orig_out(k0, k1, 0u, 2u); a1 = orig_out(k0, k1, 1u, 2u);
    b0 = orig_out(k0, k1, 2u, 2u); b1 = orig_out(k0, k1, 3u, 2u);
  }
}

// split into 3 children
__device__ __forceinline__ void split3(int mode, uint32_t k0, uint32_t k1,
                                       uint32_t& a0, uint32_t& a1,
                                       uint32_t& b0, uint32_t& b1,
                                       uint32_t& c0, uint32_t& c1) {
  if (mode < 3) {
    a0 = 0u; a1 = 0u; tf2x32(k0, k1, a0, a1);
    b0 = 0u; b1 = 1u; tf2x32(k0, k1, b0, b1);
    c0 = 0u; c1 = 2u; tf2x32(k0, k1, c0, c1);
  } else {
    a0 = orig_out(k0, k1, 0u, 3u); a1 = orig_out(k0, k1, 1u, 3u);
    b0 = orig_out(k0, k1, 2u, 3u); b1 = orig_out(k0, k1, 3u, 3u);
    c0 = orig_out(k0, k1, 4u, 3u); c1 = orig_out(k0, k1, 5u, 3u);
  }
}

// child i of split(key, n)
__device__ __forceinline__ void child_key_n(int mode, uint32_t k0, uint32_t k1,
                                            uint32_t i, uint32_t n,
                                            uint32_t& c0, uint32_t& c1) {
  if (mode < 3) {
    c0 = 0u; c1 = i; tf2x32(k0, k1, c0, c1);
  } else {
    c0 = orig_out(k0, k1, 2u * i, n);
    c1 = orig_out(k0, k1, 2u * i + 1u, n);
  }
}

__device__ __forceinline__ float bits_to_u01(uint32_t bits) {
  float f = __uint_as_float((bits >> 9) | 0x3f800000u);
  return __fadd_rn(f, -1.0f);   // [0,1)
}

// XLA ErfInv (Giles), separate mul/add rounding to match HLO
__device__ __forceinline__ float erfinv_xla(float x) {
  float t = __fmul_rn(x, x);
  float w = -log1pf(-t);
  float p;
  if (w < 5.0f) {
    w = __fadd_rn(w, -2.5f);
    p = 2.81022636e-08f;
    p = __fadd_rn(__fmul_rn(p, w), 3.43273939e-07f);
    p = __fadd_rn(__fmul_rn(p, w), -3.5233877e-06f);
    p = __fadd_rn(__fmul_rn(p, w), -4.39150654e-06f);
    p = __fadd_rn(__fmul_rn(p, w), 0.00021858087f);
    p = __fadd_rn(__fmul_rn(p, w), -0.00125372503f);
    p = __fadd_rn(__fmul_rn(p, w), -0.00417768164f);
    p = __fadd_rn(__fmul_rn(p, w), 0.246640727f);
    p = __fadd_rn(__fmul_rn(p, w), 1.50140941f);
  } else {
    w = __fadd_rn(sqrtf(w), -3.0f);
    p = -0.000200214257f;
    p = __fadd_rn(__fmul_rn(p, w), 0.000100950558f);
    p = __fadd_rn(__fmul_rn(p, w), 0.00134934322f);
    p = __fadd_rn(__fmul_rn(p, w), -0.00367342844f);
    p = __fadd_rn(__fmul_rn(p, w), 0.00573950773f);
    p = __fadd_rn(__fmul_rn(p, w), -0.0076224613f);
    p = __fadd_rn(__fmul_rn(p, w), 0.00943887047f);
    p = __fadd_rn(__fmul_rn(p, w), 1.00167406f);
    p = __fadd_rn(__fmul_rn(p, w), 2.83297682f);
  }
  return __fmul_rn(p, x);
}

// jax.random.normal(): uniform in [-0.99999994, 1), sqrt(2)*erfinv
__device__ __forceinline__ float normal_from_bits(uint32_t bits) {
  float f = bits_to_u01(bits);
  float u = __fadd_rn(__fmul_rn(f, 2.0f), -0.99999994f);
  u = fmaxf(-0.99999994f, u);
  return __fmul_rn(1.41421356237f, erfinv_xla(u));
}

// ---------------- mode detection from input x ----------------
// x = jax.random.normal(split(key(0),10)[0], (NN, CC)); reproduce x[0..3]
__global__ void k_detect(const float* __restrict__ x, int* mode_out) {
  if (threadIdx.x != 0 || blockIdx.x != 0) return;
  float best = 1e30f; int bm = 0;
  for (int m = 0; m < 4; m++) {
    uint32_t a0, a1;
    if (m < 3) { a0 = 0u; a1 = 0u; tf2x32(0u, 0u, a0, a1); }      // fold child0
    else { a0 = orig_out(0u, 0u, 0u, 10u); a1 = orig_out(0u, 0u, 1u, 10u); }
    float err = 0.0f;
    for (uint32_t t = 0; t < 4; t++) {
      uint32_t bits;
      if (m < 3) {
        uint32_t b0 = 0u, b1 = t;
        tf2x32(a0, a1, b0, b1);
        bits = (m == 0) ? (b0 ^ b1) : ((m == 1) ? b0 : b1);
      } else {
        bits = orig_out(a0, a1, t, (uint32_t)(NN * CC / 2));
      }
      err += fabsf(normal_from_bits(bits) - x[t]);
    }
    if (err < best) { best = err; bm = m; }
  }
  *mode_out = bm;
}

// ---------------- CSR build ----------------
__global__ void k_zero2(int* a, int* b, int n) {
  int i = blockIdx.x * blockDim.x + threadIdx.x;
  if (i < n) { a[i] = 0; b[i] = 0; }
}

__global__ void k_count(const int* __restrict__ dst, int E, int* __restrict__ cnt) {
  int e = blockIdx.x * blockDim.x + threadIdx.x;
  if (e < E) atomicAdd(&cnt[dst[e]], 1);
}

__global__ void k_blocksum(const int* __restrict__ cnt, int n, int* __restrict__ bsum) {
  __shared__ int s[256];
  int i = blockIdx.x * 256 + threadIdx.x;
  s[threadIdx.x] = (i < n) ? cnt[i] : 0;
  __syncthreads();
  for (int o = 128; o; o >>= 1) {
    if (threadIdx.x < o) s[threadIdx.x] += s[threadIdx.x + o];
    __syncthreads();
  }
  if (threadIdx.x == 0) bsum[blockIdx.x] = s[0];
}

__global__ void k_scan_bsum(int* bsum, int nb) {
  if (threadIdx.x == 0 && blockIdx.x == 0) {
    int s = 0;
    for (int i = 0; i < nb; i++) { int v = bsum[i]; bsum[i] = s; s += v; }
  }
}

__global__ void k_scan_final(const int* __restrict__ cnt, const int* __restrict__ bsum,
                             int n, int E, int* __restrict__ off, float* __restrict__ dinv) {
  __shared__ int s[256];
  int i = blockIdx.x * 256 + threadIdx.x;
  int v = (i < n) ? cnt[i] : 0;
  s[threadIdx.x] = v;
  __syncthreads();
  for (int o = 1; o < 256; o <<= 1) {
    int t = (threadIdx.x >= o) ? s[threadIdx.x - o] : 0;
    __syncthreads();
    s[threadIdx.x] += t;
    __syncthreads();
  }
  if (i < n) {
    int excl = s[threadIdx.x] - v;
    off[i] = excl + bsum[blockIdx.x];
    dinv[i] = rsqrtf((float)v + 1.0f);
    if (i == n - 1) off[n] = E;
  }
}

__global__ void k_fill(const int* __restrict__ src, const int* __restrict__ dst, int E,
                       const int* __restrict__ off, int* __restrict__ cur,
                       int* __restrict__ csr) {
  int e = blockIdx.x * blockDim.x + threadIdx.x;
  if (e < E) {
    int d = dst[e];
    int pos = off[d] + atomicAdd(&cur[d], 1);
    csr[pos] = src[e];
  }
}

// ---------------- fused pull aggregation + bias + relu + residual ----------------
__global__ __launch_bounds__(256) void k_pull(const float* __restrict__ h,
                                              const float* __restrict__ x,
                                              const float* __restrict__ bconv,
                                              const float* __restrict__ dinv,
                                              const int* __restrict__ off,
                                              const int* __restrict__ csr,
                                              float* __restrict__ outr, int n) {
  int gw = (blockIdx.x * blockDim.x + threadIdx.x) >> 5;
  int lane = threadIdx.x & 31;
  if (gw >= n) return;
  float dd = dinv[gw];
  float4 hv = *(const float4*)&h[(size_t)gw * CC + lane * 4];
  float sn = dd * dd;
  float4 acc = make_float4(hv.x * sn, hv.y * sn, hv.z * sn, hv.w * sn);
  int j0 = off[gw], j1 = off[gw + 1];
#pragma unroll 4
  for (int j = j0; j < j1; j++) {
    int s = csr[j];
    float norm = dinv[s] * dd;
    float4 v = *(const float4*)&h[(size_t)s * CC + lane * 4];
    acc.x += v.x * norm; acc.y += v.y * norm;
    acc.z += v.z * norm; acc.w += v.w * norm;
  }
  const float4 bv = *(const float4*)&bconv[lane * 4];
  const float4 xv = *(const float4*)&x[(size_t)gw * CC + lane * 4];
  float4 o;
  o.x = fmaxf(acc.x + bv.x, 0.0f) + xv.x;
  o.y = fmaxf(acc.y + bv.y, 0.0f) + xv.y;
  o.z = fmaxf(acc.z + bv.z, 0.0f) + xv.z;
  o.w = fmaxf(acc.w + bv.w, 0.0f) + xv.w;
  *(float4*)&outr[(size_t)gw * CC + lane * 4] = o;
}

// ---------------- SGEMM (double-buffered): C = act(A@B + bias) ----------------
__global__ __launch_bounds__(256) void k_sgemm(const float* __restrict__ A,
                                               const float* __restrict__ B,
                                               const float* __restrict__ bias,
                                               float* __restrict__ C,
                                               int M, int N, int K, int act) {
  __shared__ float As[2][16][128];
  __shared__ float Bs[2][16][128];
  int tid = threadIdx.x;
  int row0 = blockIdx.y * 128;
  int col0 = blockIdx.x * 128;
  int tr = tid >> 4;
  int tc = tid & 15;

  int ar0 = (tid * 2) >> 2,       ac0 = (tid * 2) & 3;
  int ar1 = (tid * 2 + 1) >> 2,   ac1 = (tid * 2 + 1) & 3;
  int br0 = tid >> 5,             bc0 = tid & 31;
  int br1 = 8 + br0;

  float acc[8][8];
#pragma unroll
  for (int i = 0; i < 8; i++)
#pragma unroll
    for (int j = 0; j < 8; j++) acc[i][j] = 0.0f;

  {
    float4 va0 = make_float4(0.f, 0.f, 0.f, 0.f);
    float4 va1 = va0;
    if (row0 + ar0 < M) va0 = *(const float4*)&A[(size_t)(row0 + ar0) * K + ac0 * 4];
    if (row0 + ar1 < M) va1 = *(const float4*)&A[(size_t)(row0 + ar1) * K + ac1 * 4];
    As[0][ac0 * 4 + 0][ar0] = va0.x; As[0][ac0 * 4 + 1][ar0] = va0.y;
    As[0][ac0 * 4 + 2][ar0] = va0.z; As[0][ac0 * 4 + 3][ar0] = va0.w;
    As[0][ac1 * 4 + 0][ar1] = va1.x; As[0][ac1 * 4 + 1][ar1] = va1.y;
    As[0][ac1 * 4 + 2][ar1] = va1.z; As[0][ac1 * 4 + 3][ar1] = va1.w;
    *(float4*)&Bs[0][br0][bc0 * 4] = *(const float4*)&B[(size_t)br0 * N + col0 + bc0 * 4];
    *(float4*)&Bs[0][br1][bc0 * 4] = *(const float4*)&B[(size_t)br1 * N + col0 + bc0 * 4];
  }
  __syncthreads();

  int buf = 0;
  int nIter = K / 16;
  for (int it = 0; it < nIter; it++) {
    float4 va0, va1, vb0, vb1;
    if (it + 1 < nIter) {
      int k0 = (it + 1) * 16;
      va0 = make_float4(0.f, 0.f, 0.f, 0.f);
      va1 = va0;
      if (row0 + ar0 < M) va0 = *(const float4*)&A[(size_t)(row0 + ar0) * K + k0 + ac0 * 4];
      if (row0 + ar1 < M) va1 = *(const float4*)&A[(size_t)(row0 + ar1) * K + k0 + ac1 * 4];
      vb0 = *(const float4*)&B[(size_t)(k0 + br0) * N + col0 + bc0 * 4];
      vb1 = *(const float4*)&B[(size_t)(k0 + br1) * N + col0 + bc0 * 4];
    }
#pragma unroll
    for (int kk = 0; kk < 16; kk++) {
      float a[8], b[8];
#pragma unroll
      for (int i = 0; i < 8; i++) a[i] = As[buf][kk][tr * 8 + i];
#pragma unroll
      for (int j = 0; j < 8; j++) b[j] = Bs[buf][kk][tc * 8 + j];
#pragma unroll
      for (int i = 0; i < 8; i++)
#pragma unroll
        for (int j = 0; j < 8; j++) acc[i][j] += a[i] * b[j];
    }
    if (it + 1 < nIter) {
      int nb = buf ^ 1;
      As[nb][ac0 * 4 + 0][ar0] = va0.x; As[nb][ac0 * 4 + 1][ar0] = va0.y;
      As[nb][ac0 * 4 + 2][ar0] = va0.z; As[nb][ac0 * 4 + 3][ar0] = va0.w;
      As[nb][ac1 * 4 + 0][ar1] = va1.x; As[nb][ac1 * 4 + 1][ar1] = va1.y;
      As[nb][ac1 * 4 + 2][ar1] = va1.z; As[nb][ac1 * 4 + 3][ar1] = va1.w;
      *(float4*)&Bs[nb][br0][bc0 * 4] = vb0;
      *(float4*)&Bs[nb][br1][bc0 * 4] = vb1;
      __syncthreads();
      buf = nb;
    }
  }

#pragma unroll
  for (int i = 0; i < 8; i++) {
    int grow = row0 + tr * 8 + i;
    if (grow >= M) break;
#pragma unroll
    for (int j = 0; j < 8; j += 4) {
      int gcol = col0 + tc * 8 + j;
      float4 v;
      v.x = acc[i][j + 0]; v.y = acc[i][j + 1]; v.z = acc[i][j + 2]; v.w = acc[i][j + 3];
      if (bias) {
        v.x += bias[gcol + 0]; v.y += bias[gcol + 1];
        v.z += bias[gcol + 2]; v.w += bias[gcol + 3];
      }
      if (act == 1) {
        v.x = (v.x >= 0.f) ? v.x : 0.01f * v.x;
        v.y = (v.y >= 0.f) ? v.y : 0.01f * v.y;
        v.z = (v.z >= 0.f) ? v.z : 0.01f * v.z;
        v.w = (v.w >= 0.f) ? v.w : 0.01f * v.w;
      }
      *(float4*)&C[(size_t)grow * N + gcol] = v;
    }
  }
}

// conc = softplus(h2 @ W3 + b3) + 1e-20  (one warp per row)
__global__ void k_conc(const float* __restrict__ h2, const float* __restrict__ W3,
                       const float* __restrict__ b3, float* __restrict__ conc, int M) {
  int gw = (blockIdx.x * blockDim.x + threadIdx.x) >> 5;
  int lane = threadIdx.x & 31;
  if (gw >= M) return;
  const float* row = h2 + (size_t)gw * HH;
  float s = 0.0f;
#pragma unroll
  for (int j = lane; j < HH; j += 32) s += row[j] * W3[j];
#pragma unroll
  for (int o = 16; o; o >>= 1) s += __shfl_xor_sync(0xffffffffu, s, o);
  if (lane == 0) {
    float z = s + b3[0];
    float sp = fmaxf(z, 0.0f) + log1pf(expf(-fabsf(z)));
    conc[gw] = sp + 1e-20f;
  }
}

// ---------------- JAX gamma sampler (log-space, Marsaglia-Tsang) ----------------
__global__ void k_gamma(const float* __restrict__ conc, float* __restrict__ lg_out,
                        const int* __restrict__ pmode, int n) {
  int i = blockIdx.x * blockDim.x + threadIdx.x;
  if (i >= n) return;
  int mode = *pmode;

  // per-element child key of dirichlet key(42) = (0, 42)
  uint32_t ck0, ck1;
  child_key_n(mode, 0u, 42u, (uint32_t)i, (uint32_t)n, ck0, ck1);

  // key, subkey = split(child)
  uint32_t k0, k1, s0, s1;
  split2(mode, ck0, ck1, k0, k1, s0, s1);

  float alpha_orig = conc[i];
  float u_boost = bits_to_u01(bits32(mode, s0, s1));
  float alpha = alpha_orig;
  float log_boost = 0.0f;
  if (!(alpha_orig >= 1.0f)) {
    // log_space boost: log(U) ~ -Exponential(1) = log1p(-u)  [R5 fix: was log(u)]
    log_boost = __fmul_rn(log1pf(-u_boost), __fdiv_rn(1.0f, alpha_orig));
    alpha = __fadd_rn(alpha_orig, 1.0f);
  }
  float d = __fadd_rn(alpha, -0.33333334f);
  // c = (1/3)/sqrt(d) == 1/sqrt(9d)
  float c = __fdiv_rn(0.33333334f, sqrtf(d));

  float V = 1.0f;
  for (;;) {
    uint32_t nk0, nk1, xk0, xk1, Uk0, Uk1;
    split3(mode, k0, k1, nk0, nk1, xk0, xk1, Uk0, Uk1);
    k0 = nk0; k1 = nk1;

    float x, v;
    uint32_t c0 = xk0, c1 = xk1;
    for (;;) {
      uint32_t n0, n1, sk0, sk1;
      split2(mode, c0, c1, n0, n1, sk0, sk1);
      c0 = n0; c1 = n1;
      x = normal_from_bits(bits32(mode, sk0, sk1));
      v = __fadd_rn(1.0f, __fmul_rn(x, c));
      if (!(v <= 0.0f)) break;
    }
    float X = __fmul_rn(x, x);
    V = __fmul_rn(__fmul_rn(v, v), v);
    float U = bits_to_u01(bits32(mode, Uk0, Uk1));

    bool c1b = (U >= __fsub_rn(1.0f, __fmul_rn(0.0331f, __fmul_rn(X, X))));
    if (!c1b) break;
    float rhs = __fadd_rn(__fmul_rn(X, 0.5f),
                          __fmul_rn(d, __fadd_rn(__fsub_rn(1.0f, V), logf(V))));
    if (!(logf(U) >= rhs)) break;
  }
  lg_out[i] = __fadd_rn(__fadd_rn(logf(d), logf(V)), log_boost);
}

// ---------------- per-batch-row: softmax-normalize + log_prob ----------------
__global__ void k_finalize(const float* __restrict__ lg, const float* __restrict__ conc,
                           float* __restrict__ out, int B, int A) {
  int b = blockIdx.x;
  int t = threadIdx.x;
  const float* lgr = lg + (size_t)b * A;
  const float* cr = conc + (size_t)b * A;
  __shared__ float sf[256];
  __shared__ double sd[256];

  float m = -INFINITY;
  for (int j = t; j < A; j += 256) m = fmaxf(m, lgr[j]);
  sf[t] = m; __syncthreads();
  for (int o = 128; o; o >>= 1) { if (t < o) sf[t] = fmaxf(sf[t], sf[t + o]); __syncthreads(); }
  m = sf[0]; __syncthreads();

  double se = 0.0;
  for (int j = t; j < A; j += 256) se += (double)expf(lgr[j] - m);
  sd[t] = se; __syncthreads();
  for (int o = 128; o; o >>= 1) { if (t < o) sd[t] += sd[t + o]; __syncthreads(); }
  float lse = m + logf((float)sd[0]);
  __syncthreads();

  double s1 = 0.0, s2 = 0.0, s3 = 0.0;
  for (int j = t; j < A; j += 256) {
    float a = expf(lgr[j] - lse);
    out[(size_t)b * A + j] = a;
    float cj = cr[j];
    s1 += (double)((cj - 1.0f) * logf(a));
    s2 += (double)cj;
    s3 += (double)lgammaf(cj);
  }
  sd[t] = s1; __syncthreads();
  for (int o = 128; o; o >>= 1) { if (t < o) sd[t] += sd[t + o]; __syncthreads(); }
  double S1 = sd[0]; __syncthreads();
  sd[t] = s2; __syncthreads();
  for (int o = 128; o; o >>= 1) { if (t < o) sd[t] += sd[t + o]; __syncthreads(); }
  double S2 = sd[0]; __syncthreads();
  sd[t] = s3; __syncthreads();
  for (int o = 128; o; o >>= 1) { if (t < o) sd[t] += sd[t + o]; __syncthreads(); }
  double S3 = sd[0];

  if (t == 0) {
    out[(size_t)B * A + b] = (float)(S1 + lgamma(S2) - S3);
  }
}

// ---------------- host launcher ----------------
extern "C" void kernel_launch(void* const* d_in, const int* in_sizes, int n_in,
                              void* d_out, int out_size) {
  const float* x      = (const float*)d_in[0];
  const float* W_conv = (const float*)d_in[1];
  const float* b_conv = (const float*)d_in[2];
  const float* W1     = (const float*)d_in[3];
  const float* b1     = (const float*)d_in[4];
  const float* W2     = (const float*)d_in[5];
  const float* b2     = (const float*)d_in[6];
  const float* W3     = (const float*)d_in[7];
  const float* b3     = (const float*)d_in[8];
  const int*   edge   = (const int*)d_in[9];

  int N = in_sizes[0] / CC;     // 100000
  int E = in_sizes[9] / 2;      // 1600000
  int B = N / ADIM;             // 100
  const int* src = edge;
  const int* dst = edge + E;
  float* out = (float*)d_out;

  float *ph, *pr, *pdinv, *ph1, *ph2, *pconc, *plg;
  int *pcnt, *pcur, *poff, *pbsum, *pcsr, *pmode;
  cudaGetSymbolAddress((void**)&ph,    g_h);
  cudaGetSymbolAddress((void**)&pr,    g_r);
  cudaGetSymbolAddress((void**)&pdinv, g_dinv);
  cudaGetSymbolAddress((void**)&ph1,   g_h1);
  cudaGetSymbolAddress((void**)&ph2,   g_h2);
  cudaGetSymbolAddress((void**)&pconc, g_conc);
  cudaGetSymbolAddress((void**)&plg,   g_lg);
  cudaGetSymbolAddress((void**)&pcnt,  g_cnt);
  cudaGetSymbolAddress((void**)&pcur,  g_cur);
  cudaGetSymbolAddress((void**)&poff,  g_off);
  cudaGetSymbolAddress((void**)&pbsum, g_bsum);
  cudaGetSymbolAddress((void**)&pcsr,  g_csr);
  cudaGetSymbolAddress((void**)&pmode, g_mode);

  int nb = (N + 255) / 256;

  // RNG convention detection (cheap, deterministic)
  k_detect<<<1, 32>>>(x, pmode);

  // ---- CSR build ----
  k_zero2<<<nb, 256>>>(pcnt, pcur, N);
  k_count<<<(E + 255) / 256, 256>>>(dst, E, pcnt);
  k_blocksum<<<nb, 256>>>(pcnt, N, pbsum);
  k_scan_bsum<<<1, 32>>>(pbsum, nb);
  k_scan_final<<<nb, 256>>>(pcnt, pbsum, N, E, poff, pdinv);
  k_fill<<<(E + 255) / 256, 256>>>(src, dst, E, poff, pcur, pcsr);

  // h = x @ W_conv
  {
    dim3 g(CC / 128, (N + 127) / 128);
    k_sgemm<<<g, 256>>>(x, W_conv, nullptr, ph, N, CC, CC, 0);
  }

  // fused: pull-aggregate + bias + relu + residual
  k_pull<<<(N * 32 + 255) / 256, 256>>>(ph, x, b_conv, pdinv, poff, pcsr, pr, N);

  // MLP
  {
    dim3 g(HH / 128, (N + 127) / 128);
    k_sgemm<<<g, 256>>>(pr, W1, b1, ph1, N, HH, CC, 1);
  }
  {
    dim3 g(HH / 128, (N + 127) / 128);
    k_sgemm<<<g, 256>>>(ph1, W2, b2, ph2, N, HH, HH, 1);
  }
  k_conc<<<(N * 32 + 255) / 256, 256>>>(ph2, W3, b3, pconc, N);

  // Dirichlet
  k_gamma<<<(N + 255) / 256, 256>>>(pconc, plg, pmode, N);
  k_finalize<<<B, 256>>>(plg, pconc, out, B, ADIM);
}

// round 16
// speedup vs baseline: 1.2338x; 1.2338x over previous
#include <cuda_runtime.h>
#include <cuda_bf16.h>
#include <cstdint>
#include <math.h>

#define NN 100000
#define CC 128
#define HH 256
#define ADIM 1000
#define EE_MAX 1700000

// ---------------- device scratch (no allocations allowed) ----------------
static __device__ float g_h[(size_t)NN * CC];     // conv linear output
static __device__ float g_r[(size_t)NN * CC];     // aggregated / residual
static __device__ float g_dinv[NN];               // rsqrt(deg) incl self-loop
static __device__ int   g_cnt[NN];                // in-degree counts
static __device__ int   g_cur[NN];                // bucket cursors
static __device__ int   g_off[NN + 1];            // CSR offsets
static __device__ int   g_bsum[512];              // block sums for scan
static __device__ int   g_csr[EE_MAX];            // CSR src lists
static __device__ float g_h1[(size_t)NN * HH];
static __device__ float g_h2[(size_t)NN * HH];
static __device__ float g_conc[NN];
static __device__ float g_lg[NN];                 // log-gamma samples
static __device__ int   g_mode;                   // detected RNG convention
static __device__ int   g_bad;                    // mma self-check flag

// ---------------- threefry2x32 block (JAX-exact) ----------------
__device__ __forceinline__ void tf2x32(uint32_t k0, uint32_t k1,
                                       uint32_t& x0, uint32_t& x1) {
  uint32_t k2 = k0 ^ k1 ^ 0x1BD11BDAu;
  x0 += k0; x1 += k1;
#define TF_R(r) { x0 += x1; x1 = (x1 << (r)) | (x1 >> (32 - (r))); x1 ^= x0; }
  TF_R(13) TF_R(15) TF_R(26) TF_R(6)
  x0 += k1; x1 += k2 + 1u;
  TF_R(17) TF_R(29) TF_R(16) TF_R(24)
  x0 += k2; x1 += k0 + 2u;
  TF_R(13) TF_R(15) TF_R(26) TF_R(6)
  x0 += k0; x1 += k1 + 3u;
  TF_R(17) TF_R(29) TF_R(16) TF_R(24)
  x0 += k1; x1 += k2 + 4u;
  TF_R(13) TF_R(15) TF_R(26) TF_R(6)
  x0 += k2; x1 += k0 + 5u;
#undef TF_R
}

__device__ __forceinline__ uint32_t orig_out(uint32_t k0, uint32_t k1,
                                             uint32_t m, uint32_t n) {
  uint32_t o0, o1;
  if (m < n) { o0 = m;     o1 = n + m; }
  else       { o0 = m - n; o1 = m;     }
  tf2x32(k0, k1, o0, o1);
  return (m < n) ? o0 : o1;
}

__device__ __forceinline__ uint32_t bits32(int mode, uint32_t k0, uint32_t k1) {
  uint32_t a = 0u, b = 0u;
  tf2x32(k0, k1, a, b);
  if (mode == 0) return a ^ b;
  if (mode == 2) return b;
  return a;
}

__device__ __forceinline__ void split2(int mode, uint32_t k0, uint32_t k1,
                                       uint32_t& a0, uint32_t& a1,
                                       uint32_t& b0, uint32_t& b1) {
  if (mode < 3) {
    a0 = 0u; a1 = 0u; tf2x32(k0, k1, a0, a1);
    b0 = 0u; b1 = 1u; tf2x32(k0, k1, b0, b1);
  } else {
    a0 = orig_out(k0, k1, 0u, 2u); a1 = orig_out(k0, k1, 1u, 2u);
    b0 = orig_out(k0, k1, 2u, 2u); b1 = orig_out(k0, k1, 3u, 2u);
  }
}

__device__ __forceinline__ void split3(int mode, uint32_t k0, uint32_t k1,
                                       uint32_t& a0, uint32_t& a1,
                                       uint32_t& b0, uint32_t& b1,
                                       uint32_t& c0, uint32_t& c1) {
  if (mode < 3) {
    a0 = 0u; a1 = 0u; tf2x32(k0, k1, a0, a1);
    b0 = 0u; b1 = 1u; tf2x32(k0, k1, b0, b1);
    c0 = 0u; c1 = 2u; tf2x32(k0, k1, c0, c1);
  } else {
    a0 = orig_out(k0, k1, 0u, 3u); a1 = orig_out(k0, k1, 1u, 3u);
    b0 = orig_out(k0, k1, 2u, 3u); b1 = orig_out(k0, k1, 3u, 3u);
    c0 = orig_out(k0, k1, 4u, 3u); c1 = orig_out(k0, k1, 5u, 3u);
  }
}

__device__ __forceinline__ void child_key_n(int mode, uint32_t k0, uint32_t k1,
                                            uint32_t i, uint32_t n,
                                            uint32_t& c0, uint32_t& c1) {
  if (mode < 3) {
    c0 = 0u; c1 = i; tf2x32(k0, k1, c0, c1);
  } else {
    c0 = orig_out(k0, k1, 2u * i, n);
    c1 = orig_out(k0, k1, 2u * i + 1u, n);
  }
}

__device__ __forceinline__ float bits_to_u01(uint32_t bits) {
  float f = __uint_as_float((bits >> 9) | 0x3f800000u);
  return __fadd_rn(f, -1.0f);
}

__device__ __forceinline__ float erfinv_xla(float x) {
  float t = __fmul_rn(x, x);
  float w = -log1pf(-t);
  float p;
  if (w < 5.0f) {
    w = __fadd_rn(w, -2.5f);
    p = 2.81022636e-08f;
    p = __fadd_rn(__fmul_rn(p, w), 3.43273939e-07f);
    p = __fadd_rn(__fmul_rn(p, w), -3.5233877e-06f);
    p = __fadd_rn(__fmul_rn(p, w), -4.39150654e-06f);
    p = __fadd_rn(__fmul_rn(p, w), 0.00021858087f);
    p = __fadd_rn(__fmul_rn(p, w), -0.00125372503f);
    p = __fadd_rn(__fmul_rn(p, w), -0.00417768164f);
    p = __fadd_rn(__fmul_rn(p, w), 0.246640727f);
    p = __fadd_rn(__fmul_rn(p, w), 1.50140941f);
  } else {
    w = __fadd_rn(sqrtf(w), -3.0f);
    p = -0.000200214257f;
    p = __fadd_rn(__fmul_rn(p, w), 0.000100950558f);
    p = __fadd_rn(__fmul_rn(p, w), 0.00134934322f);
    p = __fadd_rn(__fmul_rn(p, w), -0.00367342844f);
    p = __fadd_rn(__fmul_rn(p, w), 0.00573950773f);
    p = __fadd_rn(__fmul_rn(p, w), -0.0076224613f);
    p = __fadd_rn(__fmul_rn(p, w), 0.00943887047f);
    p = __fadd_rn(__fmul_rn(p, w), 1.00167406f);
    p = __fadd_rn(__fmul_rn(p, w), 2.83297682f);
  }
  return __fmul_rn(p, x);
}

__device__ __forceinline__ float normal_from_bits(uint32_t bits) {
  float f = bits_to_u01(bits);
  float u = __fadd_rn(__fmul_rn(f, 2.0f), -0.99999994f);
  u = fmaxf(-0.99999994f, u);
  return __fmul_rn(1.41421356237f, erfinv_xla(u));
}

// ---------------- mode detection from input x (also clears g_bad) ----------------
__global__ void k_detect(const float* __restrict__ x, int* mode_out, int* bad) {
  if (threadIdx.x != 0 || blockIdx.x != 0) return;
  *bad = 0;
  float best = 1e30f; int bm = 0;
  for (int m = 0; m < 4; m++) {
    uint32_t a0, a1;
    if (m < 3) { a0 = 0u; a1 = 0u; tf2x32(0u, 0u, a0, a1); }
    else { a0 = orig_out(0u, 0u, 0u, 10u); a1 = orig_out(0u, 0u, 1u, 10u); }
    float err = 0.0f;
    for (uint32_t t = 0; t < 4; t++) {
      uint32_t bits;
      if (m < 3) {
        uint32_t b0 = 0u, b1 = t;
        tf2x32(a0, a1, b0, b1);
        bits = (m == 0) ? (b0 ^ b1) : ((m == 1) ? b0 : b1);
      } else {
        bits = orig_out(a0, a1, t, (uint32_t)(NN * CC / 2));
      }
      err += fabsf(normal_from_bits(bits) - x[t]);
    }
    if (err < best) { best = err; bm = m; }
  }
  *mode_out = bm;
}

// ---------------- CSR build ----------------
__global__ void k_zero2(int* a, int* b, int n) {
  int i = blockIdx.x * blockDim.x + threadIdx.x;
  if (i < n) { a[i] = 0; b[i] = 0; }
}

__global__ void k_count(const int* __restrict__ dst, int E, int* __restrict__ cnt) {
  int e = blockIdx.x * blockDim.x + threadIdx.x;
  if (e < E) atomicAdd(&cnt[dst[e]], 1);
}

__global__ void k_blocksum(const int* __restrict__ cnt, int n, int* __restrict__ bsum) {
  __shared__ int s[256];
  int i = blockIdx.x * 256 + threadIdx.x;
  s[threadIdx.x] = (i < n) ? cnt[i] : 0;
  __syncthreads();
  for (int o = 128; o; o >>= 1) {
    if (threadIdx.x < o) s[threadIdx.x] += s[threadIdx.x + o];
    __syncthreads();
  }
  if (threadIdx.x == 0) bsum[blockIdx.x] = s[0];
}

__global__ void k_scan_bsum(int* bsum, int nb) {
  if (threadIdx.x == 0 && blockIdx.x == 0) {
    int s = 0;
    for (int i = 0; i < nb; i++) { int v = bsum[i]; bsum[i] = s; s += v; }
  }
}

__global__ void k_scan_final(const int* __restrict__ cnt, const int* __restrict__ bsum,
                             int n, int E, int* __restrict__ off, float* __restrict__ dinv) {
  __shared__ int s[256];
  int i = blockIdx.x * 256 + threadIdx.x;
  int v = (i < n) ? cnt[i] : 0;
  s[threadIdx.x] = v;
  __syncthreads();
  for (int o = 1; o < 256; o <<= 1) {
    int t = (threadIdx.x >= o) ? s[threadIdx.x - o] : 0;
    __syncthreads();
    s[threadIdx.x] += t;
    __syncthreads();
  }
  if (i < n) {
    int excl = s[threadIdx.x] - v;
    off[i] = excl + bsum[blockIdx.x];
    dinv[i] = rsqrtf((float)v + 1.0f);
    if (i == n - 1) off[n] = E;
  }
}

__global__ void k_fill(const int* __restrict__ src, const int* __restrict__ dst, int E,
                       const int* __restrict__ off, int* __restrict__ cur,
                       int* __restrict__ csr) {
  int e = blockIdx.x * blockDim.x + threadIdx.x;
  if (e < E) {
    int d = dst[e];
    int pos = off[d] + atomicAdd(&cur[d], 1);
    csr[pos] = src[e];
  }
}

// ---------------- fused pull aggregation + bias + relu + residual ----------------
__global__ __launch_bounds__(256) void k_pull(const float* __restrict__ h,
                                              const float* __restrict__ x,
                                              const float* __restrict__ bconv,
                                              const float* __restrict__ dinv,
                                              const int* __restrict__ off,
                                              const int* __restrict__ csr,
                                              float* __restrict__ outr, int n) {
  int gw = (blockIdx.x * blockDim.x + threadIdx.x) >> 5;
  int lane = threadIdx.x & 31;
  if (gw >= n) return;
  float dd = dinv[gw];
  float4 hv = *(const float4*)&h[(size_t)gw * CC + lane * 4];
  float sn = dd * dd;
  float4 acc = make_float4(hv.x * sn, hv.y * sn, hv.z * sn, hv.w * sn);
  int j0 = off[gw], j1 = off[gw + 1];
#pragma unroll 4
  for (int j = j0; j < j1; j++) {
    int s = csr[j];
    float norm = dinv[s] * dd;
    float4 v = *(const float4*)&h[(size_t)s * CC + lane * 4];
    acc.x += v.x * norm; acc.y += v.y * norm;
    acc.z += v.z * norm; acc.w += v.w * norm;
  }
  const float4 bv = *(const float4*)&bconv[lane * 4];
  const float4 xv = *(const float4*)&x[(size_t)gw * CC + lane * 4];
  float4 o;
  o.x = fmaxf(acc.x + bv.x, 0.0f) + xv.x;
  o.y = fmaxf(acc.y + bv.y, 0.0f) + xv.y;
  o.z = fmaxf(acc.z + bv.z, 0.0f) + xv.z;
  o.w = fmaxf(acc.w + bv.w, 0.0f) + xv.w;
  *(float4*)&outr[(size_t)gw * CC + lane * 4] = o;
}

// ============ mma.sync bf16 x6 (emulated fp32) GEMM — sm_80+ PTX ============
// C[M,N] = act(A[M,K] @ B[K,N] + bias). Block tile 128x128, BK=16, 256 thr.
// A,B split into 3 exact bf16 pieces (hi/mid/lo); 6 products -> err ~2^-24.
// Smem: As[p][m][k] (128x16, stride 18), Bs[p][n][k] transposed (128x16).

#define SA 18   // bf16 element stride per row (pad to dodge conflicts, keeps 4B align)

__device__ __forceinline__ void bf16_split3(float a, __nv_bfloat16& hi,
                                            __nv_bfloat16& mi, __nv_bfloat16& lo) {
  hi = __float2bfloat16(a);
  float r1 = __fsub_rn(a, __bfloat162float(hi));
  mi = __float2bfloat16(r1);
  float r2 = __fsub_rn(r1, __bfloat162float(mi));
  lo = __float2bfloat16(r2);
}

__device__ __forceinline__ void mma_bf16(float* c, const uint32_t* a, const uint32_t* b) {
  asm volatile(
      "mma.sync.aligned.m16n8k16.row.col.f32.bf16.bf16.f32 "
      "{%0,%1,%2,%3}, {%4,%5,%6,%7}, {%8,%9}, {%0,%1,%2,%3};"
      : "+f"(c[0]), "+f"(c[1]), "+f"(c[2]), "+f"(c[3])
      : "r"(a[0]), "r"(a[1]), "r"(a[2]), "r"(a[3]), "r"(b[0]), "r"(b[1]));
}

__global__ __launch_bounds__(256) void k_mmagemm(const float* __restrict__ A,
                                                 const float* __restrict__ B,
                                                 const float* __restrict__ bias,
                                                 float* __restrict__ C,
                                                 int M, int N, int K, int act) {
  __shared__ __align__(16) __nv_bfloat16 As[3][128 * SA];
  __shared__ __align__(16) __nv_bfloat16 Bs[3][128 * SA];
  int tid = threadIdx.x;
  int w = tid >> 5, lane = tid & 31;
  int g = lane >> 2, tg = lane & 3;
  int row0 = blockIdx.y * 128, col0 = blockIdx.x * 128;
  int wr = w >> 2, wc = w & 3;           // warp grid 2 x 4 -> 64x32 per warp

  float acc[4][4][4];
#pragma unroll
  for (int i = 0; i < 4; i++)
#pragma unroll
    for (int j = 0; j < 4; j++)
#pragma unroll
      for (int q = 0; q < 4; q++) acc[i][j][q] = 0.0f;

  // per-thread load coords
  int am = tid >> 1, ak = (tid & 1) * 8;        // A: 128 rows x 16 k
  int bk = tid >> 4, bn = (tid & 15) * 8;       // B: 16 k x 128 n

  for (int k0 = 0; k0 < K; k0 += 16) {
    if (k0) __syncthreads();                    // previous compute done
    // A tile -> split -> As[p][m][k]
    {
      float v[8];
      if (row0 + am < M) {
        float4 u0 = *(const float4*)&A[(size_t)(row0 + am) * K + k0 + ak];
        float4 u1 = *(const float4*)&A[(size_t)(row0 + am) * K + k0 + ak + 4];
        v[0] = u0.x; v[1] = u0.y; v[2] = u0.z; v[3] = u0.w;
        v[4] = u1.x; v[5] = u1.y; v[6] = u1.z; v[7] = u1.w;
      } else {
#pragma unroll
        for (int e = 0; e < 8; e++) v[e] = 0.0f;
      }
#pragma unroll
      for (int e = 0; e < 8; e++) {
        __nv_bfloat16 hi, mi, lo;
        bf16_split3(v[e], hi, mi, lo);
        int idx = am * SA + ak + e;
        As[0][idx] = hi; As[1][idx] = mi; As[2][idx] = lo;
      }
    }
    // B tile -> split -> Bs[p][n][k] (transposed)
    {
      float4 u0 = *(const float4*)&B[(size_t)(k0 + bk) * N + col0 + bn];
      float4 u1 = *(const float4*)&B[(size_t)(k0 + bk) * N + col0 + bn + 4];
      float v[8] = {u0.x, u0.y, u0.z, u0.w, u1.x, u1.y, u1.z, u1.w};
#pragma unroll
      for (int e = 0; e < 8; e++) {
        __nv_bfloat16 hi, mi, lo;
        bf16_split3(v[e], hi, mi, lo);
        int idx = (bn + e) * SA + bk;
        Bs[0][idx] = hi; Bs[1][idx] = mi; Bs[2][idx] = lo;
      }
    }
    __syncthreads();

#pragma unroll
    for (int i = 0; i < 4; i++) {
      int ma = wr * 64 + i * 16;
      uint32_t a[3][4];
#pragma unroll
      for (int p = 0; p < 3; p++) {
        a[p][0] = *(const uint32_t*)&As[p][(ma + g) * SA + tg * 2];
        a[p][1] = *(const uint32_t*)&As[p][(ma + g + 8) * SA + tg * 2];
        a[p][2] = *(const uint32_t*)&As[p][(ma + g) * SA + tg * 2 + 8];
        a[p][3] = *(const uint32_t*)&As[p][(ma + g + 8) * SA + tg * 2 + 8];
      }
#pragma unroll
      for (int j = 0; j < 4; j++) {
        int na = wc * 32 + j * 8;
        uint32_t b[3][2];
#pragma unroll
        for (int p = 0; p < 3; p++) {
          b[p][0] = *(const uint32_t*)&Bs[p][(na + g) * SA + tg * 2];
          b[p][1] = *(const uint32_t*)&Bs[p][(na + g) * SA + tg * 2 + 8];
        }
        float* c = acc[i][j];
        mma_bf16(c, a[0], b[0]);   // hi*hi
        mma_bf16(c, a[0], b[1]);   // hi*mid
        mma_bf16(c, a[1], b[0]);   // mid*hi
        mma_bf16(c, a[1], b[1]);   // mid*mid
        mma_bf16(c, a[0], b[2]);   // hi*lo
        mma_bf16(c, a[2], b[0]);   // lo*hi
      }
    }
  }

  // epilogue: c0=C[g][tg*2], c1=+1col, c2/c3 = rows+8
#pragma unroll
  for (int i = 0; i < 4; i++) {
    int ma = row0 + wr * 64 + i * 16;
#pragma unroll
    for (int j = 0; j < 4; j++) {
      int na = col0 + wc * 32 + j * 8 + tg * 2;
      float b0 = 0.f, b1 = 0.f;
      if (bias) { b0 = bias[na]; b1 = bias[na + 1]; }
#pragma unroll
      for (int half = 0; half < 2; half++) {
        int row = ma + g + half * 8;
        if (row < M) {
          float v0 = acc[i][j][half * 2 + 0] + b0;
          float v1 = acc[i][j][half * 2 + 1] + b1;
          if (act == 1) {
            v0 = (v0 >= 0.f) ? v0 : 0.01f * v0;
            v1 = (v1 >= 0.f) ? v1 : 0.01f * v1;
          }
          float2 st; st.x = v0; st.y = v1;
          *(float2*)&C[(size_t)row * N + na] = st;
        }
      }
    }
  }
}

// sampled SIMT verification of mma output; sets *bad on mismatch/NaN
__global__ void k_check(const float* __restrict__ A, const float* __restrict__ B,
                        const float* __restrict__ bias, const float* __restrict__ Ct,
                        int M, int N, int K, int act, int* bad) {
  int i = threadIdx.x;                         // 32 samples
  int row = (int)(((long long)i * 92821 + 13) % M);
  int col = (int)(((long long)i * 733 + 5) % N);
  float s = 0.0f;
  for (int k = 0; k < K; k++) s += A[(size_t)row * K + k] * B[(size_t)k * N + col];
  if (bias) s += bias[col];
  if (act == 1) s = (s >= 0.f) ? s : 0.01f * s;
  float got = Ct[(size_t)row * N + col];
  float diff = fabsf(got - s);
  if (!(diff <= 1e-2f * (fabsf(s) + 1.0f))) atomicOr(bad, 1);
}

// ---------------- guarded SIMT fallback GEMM (runs only if g_bad) ----------------
__global__ __launch_bounds__(256) void k_sgemm_guard(const float* __restrict__ A,
                                                     const float* __restrict__ B,
                                                     const float* __restrict__ bias,
                                                     float* __restrict__ C,
                                                     int M, int N, int K, int act,
                                                     const int* __restrict__ bad) {
  if (*bad == 0) return;
  __shared__ float As[2][16][128];
  __shared__ float Bs[2][16][128];
  int tid = threadIdx.x;
  int row0 = blockIdx.y * 128;
  int col0 = blockIdx.x * 128;
  int tr = tid >> 4;
  int tc = tid & 15;

  int ar0 = (tid * 2) >> 2,     ac0 = (tid * 2) & 3;
  int ar1 = (tid * 2 + 1) >> 2, ac1 = (tid * 2 + 1) & 3;
  int br0 = tid >> 5,           bc0 = tid & 31;
  int br1 = 8 + br0;

  float acc[8][8];
#pragma unroll
  for (int i = 0; i < 8; i++)
#pragma unroll
    for (int j = 0; j < 8; j++) acc[i][j] = 0.0f;

  {
    float4 va0 = make_float4(0.f, 0.f, 0.f, 0.f);
    float4 va1 = va0;
    if (row0 + ar0 < M) va0 = *(const float4*)&A[(size_t)(row0 + ar0) * K + ac0 * 4];
    if (row0 + ar1 < M) va1 = *(const float4*)&A[(size_t)(row0 + ar1) * K + ac1 * 4];
    As[0][ac0 * 4 + 0][ar0] = va0.x; As[0][ac0 * 4 + 1][ar0] = va0.y;
    As[0][ac0 * 4 + 2][ar0] = va0.z; As[0][ac0 * 4 + 3][ar0] = va0.w;
    As[0][ac1 * 4 + 0][ar1] = va1.x; As[0][ac1 * 4 + 1][ar1] = va1.y;
    As[0][ac1 * 4 + 2][ar1] = va1.z; As[0][ac1 * 4 + 3][ar1] = va1.w;
    *(float4*)&Bs[0][br0][bc0 * 4] = *(const float4*)&B[(size_t)br0 * N + col0 + bc0 * 4];
    *(float4*)&Bs[0][br1][bc0 * 4] = *(const float4*)&B[(size_t)br1 * N + col0 + bc0 * 4];
  }
  __syncthreads();

  int buf = 0;
  int nIter = K / 16;
  for (int it = 0; it < nIter; it++) {
    float4 va0, va1, vb0, vb1;
    if (it + 1 < nIter) {
      int k0 = (it + 1) * 16;
      va0 = make_float4(0.f, 0.f, 0.f, 0.f);
      va1 = va0;
      if (row0 + ar0 < M) va0 = *(const float4*)&A[(size_t)(row0 + ar0) * K + k0 + ac0 * 4];
      if (row0 + ar1 < M) va1 = *(const float4*)&A[(size_t)(row0 + ar1) * K + k0 + ac1 * 4];
      vb0 = *(const float4*)&B[(size_t)(k0 + br0) * N + col0 + bc0 * 4];
      vb1 = *(const float4*)&B[(size_t)(k0 + br1) * N + col0 + bc0 * 4];
    }
#pragma unroll
    for (int kk = 0; kk < 16; kk++) {
      float a[8], b[8];
#pragma unroll
      for (int i = 0; i < 8; i++) a[i] = As[buf][kk][tr * 8 + i];
#pragma unroll
      for (int j = 0; j < 8; j++) b[j] = Bs[buf][kk][tc * 8 + j];
#pragma unroll
      for (int i = 0; i < 8; i++)
#pragma unroll
        for (int j = 0; j < 8; j++) acc[i][j] += a[i] * b[j];
    }
    if (it + 1 < nIter) {
      int nb = buf ^ 1;
      As[nb][ac0 * 4 + 0][ar0] = va0.x; As[nb][ac0 * 4 + 1][ar0] = va0.y;
      As[nb][ac0 * 4 + 2][ar0] = va0.z; As[nb][ac0 * 4 + 3][ar0] = va0.w;
      As[nb][ac1 * 4 + 0][ar1] = va1.x; As[nb][ac1 * 4 + 1][ar1] = va1.y;
      As[nb][ac1 * 4 + 2][ar1] = va1.z; As[nb][ac1 * 4 + 3][ar1] = va1.w;
      *(float4*)&Bs[nb][br0][bc0 * 4] = vb0;
      *(float4*)&Bs[nb][br1][bc0 * 4] = vb1;
      __syncthreads();
      buf = nb;
    }
  }

#pragma unroll
  for (int i = 0; i < 8; i++) {
    int grow = row0 + tr * 8 + i;
    if (grow >= M) break;
#pragma unroll
    for (int j = 0; j < 8; j += 4) {
      int gcol = col0 + tc * 8 + j;
      float4 v;
      v.x = acc[i][j + 0]; v.y = acc[i][j + 1]; v.z = acc[i][j + 2]; v.w = acc[i][j + 3];
      if (bias) {
        v.x += bias[gcol + 0]; v.y += bias[gcol + 1];
        v.z += bias[gcol + 2]; v.w += bias[gcol + 3];
      }
      if (act == 1) {
        v.x = (v.x >= 0.f) ? v.x : 0.01f * v.x;
        v.y = (v.y >= 0.f) ? v.y : 0.01f * v.y;
        v.z = (v.z >= 0.f) ? v.z : 0.01f * v.z;
        v.w = (v.w >= 0.f) ? v.w : 0.01f * v.w;
      }
      *(float4*)&C[(size_t)grow * N + gcol] = v;
    }
  }
}

// conc = softplus(h2 @ W3 + b3) + 1e-20  (one warp per row)
__global__ void k_conc(const float* __restrict__ h2, const float* __restrict__ W3,
                       const float* __restrict__ b3, float* __restrict__ conc, int M) {
  int gw = (blockIdx.x * blockDim.x + threadIdx.x) >> 5;
  int lane = threadIdx.x & 31;
  if (gw >= M) return;
  const float* row = h2 + (size_t)gw * HH;
  float s = 0.0f;
#pragma unroll
  for (int j = lane; j < HH; j += 32) s += row[j] * W3[j];
#pragma unroll
  for (int o = 16; o; o >>= 1) s += __shfl_xor_sync(0xffffffffu, s, o);
  if (lane == 0) {
    float z = s + b3[0];
    float sp = fmaxf(z, 0.0f) + log1pf(expf(-fabsf(z)));
    conc[gw] = sp + 1e-20f;
  }
}

// ---------------- JAX gamma sampler (log-space, Marsaglia-Tsang) ----------------
__global__ void k_gamma(const float* __restrict__ conc, float* __restrict__ lg_out,
                        const int* __restrict__ pmode, int n) {
  int i = blockIdx.x * blockDim.x + threadIdx.x;
  if (i >= n) return;
  int mode = *pmode;

  uint32_t ck0, ck1;
  child_key_n(mode, 0u, 42u, (uint32_t)i, (uint32_t)n, ck0, ck1);

  uint32_t k0, k1, s0, s1;
  split2(mode, ck0, ck1, k0, k1, s0, s1);

  float alpha_orig = conc[i];
  float u_boost = bits_to_u01(bits32(mode, s0, s1));
  float alpha = alpha_orig;
  float log_boost = 0.0f;
  if (!(alpha_orig >= 1.0f)) {
    log_boost = __fmul_rn(log1pf(-u_boost), __fdiv_rn(1.0f, alpha_orig));
    alpha = __fadd_rn(alpha_orig, 1.0f);
  }
  float d = __fadd_rn(alpha, -0.33333334f);
  float c = __fdiv_rn(0.33333334f, sqrtf(d));

  float V = 1.0f;
  for (;;) {
    uint32_t nk0, nk1, xk0, xk1, Uk0, Uk1;
    split3(mode, k0, k1, nk0, nk1, xk0, xk1, Uk0, Uk1);
    k0 = nk0; k1 = nk1;

    float x, v;
    uint32_t c0 = xk0, c1 = xk1;
    for (;;) {
      uint32_t n0, n1, sk0, sk1;
      split2(mode, c0, c1, n0, n1, sk0, sk1);
      c0 = n0; c1 = n1;
      x = normal_from_bits(bits32(mode, sk0, sk1));
      v = __fadd_rn(1.0f, __fmul_rn(x, c));
      if (!(v <= 0.0f)) break;
    }
    float X = __fmul_rn(x, x);
    V = __fmul_rn(__fmul_rn(v, v), v);
    float U = bits_to_u01(bits32(mode, Uk0, Uk1));

    bool c1b = (U >= __fsub_rn(1.0f, __fmul_rn(0.0331f, __fmul_rn(X, X))));
    if (!c1b) break;
    float rhs = __fadd_rn(__fmul_rn(X, 0.5f),
                          __fmul_rn(d, __fadd_rn(__fsub_rn(1.0f, V), logf(V))));
    if (!(logf(U) >= rhs)) break;
  }
  lg_out[i] = __fadd_rn(__fadd_rn(logf(d), logf(V)), log_boost);
}

// ---------------- per-batch-row: softmax-normalize + log_prob ----------------
__global__ void k_finalize(const float* __restrict__ lg, const float* __restrict__ conc,
                           float* __restrict__ out, int B, int A) {
  int b = blockIdx.x;
  int t = threadIdx.x;
  const float* lgr = lg + (size_t)b * A;
  const float* cr = conc + (size_t)b * A;
  __shared__ float sf[256];
  __shared__ double sd[256];

  float m = -INFINITY;
  for (int j = t; j < A; j += 256) m = fmaxf(m, lgr[j]);
  sf[t] = m; __syncthreads();
  for (int o = 128; o; o >>= 1) { if (t < o) sf[t] = fmaxf(sf[t], sf[t + o]); __syncthreads(); }
  m = sf[0]; __syncthreads();

  double se = 0.0;
  for (int j = t; j < A; j += 256) se += (double)expf(lgr[j] - m);
  sd[t] = se; __syncthreads();
  for (int o = 128; o; o >>= 1) { if (t < o) sd[t] += sd[t + o]; __syncthreads(); }
  float lse = m + logf((float)sd[0]);
  __syncthreads();

  double s1 = 0.0, s2 = 0.0, s3 = 0.0;
  for (int j = t; j < A; j += 256) {
    float a = expf(lgr[j] - lse);
    out[(size_t)b * A + j] = a;
    float cj = cr[j];
    s1 += (double)((cj - 1.0f) * logf(a));
    s2 += (double)cj;
    s3 += (double)lgammaf(cj);
  }
  sd[t] = s1; __syncthreads();
  for (int o = 128; o; o >>= 1) { if (t < o) sd[t] += sd[t + o]; __syncthreads(); }
  double S1 = sd[0]; __syncthreads();
  sd[t] = s2; __syncthreads();
  for (int o = 128; o; o >>= 1) { if (t < o) sd[t] += sd[t + o]; __syncthreads(); }
  double S2 = sd[0]; __syncthreads();
  sd[t] = s3; __syncthreads();
  for (int o = 128; o; o >>= 1) { if (t < o) sd[t] += sd[t + o]; __syncthreads(); }
  double S3 = sd[0];

  if (t == 0) {
    out[(size_t)B * A + b] = (float)(S1 + lgamma(S2) - S3);
  }
}

// ---------------- host launcher ----------------
extern "C" void kernel_launch(void* const* d_in, const int* in_sizes, int n_in,
                              void* d_out, int out_size) {
  const float* x      = (const float*)d_in[0];
  const float* W_conv = (const float*)d_in[1];
  const float* b_conv = (const float*)d_in[2];
  const float* W1     = (const float*)d_in[3];
  const float* b1     = (const float*)d_in[4];
  const float* W2     = (const float*)d_in[5];
  const float* b2     = (const float*)d_in[6];
  const float* W3     = (const float*)d_in[7];
  const float* b3     = (const float*)d_in[8];
  const int*   edge   = (const int*)d_in[9];

  int N = in_sizes[0] / CC;     // 100000
  int E = in_sizes[9] / 2;      // 1600000
  int B = N / ADIM;             // 100
  const int* src = edge;
  const int* dst = edge + E;
  float* out = (float*)d_out;

  float *ph, *pr, *pdinv, *ph1, *ph2, *pconc, *plg;
  int *pcnt, *pcur, *poff, *pbsum, *pcsr, *pmode, *pbad;
  cudaGetSymbolAddress((void**)&ph,    g_h);
  cudaGetSymbolAddress((void**)&pr,    g_r);
  cudaGetSymbolAddress((void**)&pdinv, g_dinv);
  cudaGetSymbolAddress((void**)&ph1,   g_h1);
  cudaGetSymbolAddress((void**)&ph2,   g_h2);
  cudaGetSymbolAddress((void**)&pconc, g_conc);
  cudaGetSymbolAddress((void**)&plg,   g_lg);
  cudaGetSymbolAddress((void**)&pcnt,  g_cnt);
  cudaGetSymbolAddress((void**)&pcur,  g_cur);
  cudaGetSymbolAddress((void**)&poff,  g_off);
  cudaGetSymbolAddress((void**)&pbsum, g_bsum);
  cudaGetSymbolAddress((void**)&pcsr,  g_csr);
  cudaGetSymbolAddress((void**)&pmode, g_mode);
  cudaGetSymbolAddress((void**)&pbad,  g_bad);

  int nb = (N + 255) / 256;
  int mrows = (N + 127) / 128;

  // RNG convention detection + clear self-check flag
  k_detect<<<1, 32>>>(x, pmode, pbad);

  // ---- CSR build ----
  k_zero2<<<nb, 256>>>(pcnt, pcur, N);
  k_count<<<(E + 255) / 256, 256>>>(dst, E, pcnt);
  k_blocksum<<<nb, 256>>>(pcnt, N, pbsum);
  k_scan_bsum<<<1, 32>>>(pbsum, nb);
  k_scan_final<<<nb, 256>>>(pcnt, pbsum, N, E, poff, pdinv);
  k_fill<<<(E + 255) / 256, 256>>>(src, dst, E, poff, pcur, pcsr);

  // h = x @ W_conv  (tensor-core mma + verify + guarded fallback)
  {
    dim3 g(CC / 128, mrows);
    k_mmagemm<<<g, 256>>>(x, W_conv, nullptr, ph, N, CC, CC, 0);
    k_check<<<1, 32>>>(x, W_conv, nullptr, ph, N, CC, CC, 0, pbad);
    k_sgemm_guard<<<g, 256>>>(x, W_conv, nullptr, ph, N, CC, CC, 0, pbad);
  }

  // fused: pull-aggregate + bias + relu + residual
  k_pull<<<(N * 32 + 255) / 256, 256>>>(ph, x, b_conv, pdinv, poff, pcsr, pr, N);

  // h1 = leaky(r @ W1 + b1)
  {
    dim3 g(HH / 128, mrows);
    k_mmagemm<<<g, 256>>>(pr, W1, b1, ph1, N, HH, CC, 1);
    k_check<<<1, 32>>>(pr, W1, b1, ph1, N, HH, CC, 1, pbad);
    k_sgemm_guard<<<g, 256>>>(pr, W1, b1, ph1, N, HH, CC, 1, pbad);
  }
  // h2 = leaky(h1 @ W2 + b2)
  {
    dim3 g(HH / 128, mrows);
    k_mmagemm<<<g, 256>>>(ph1, W2, b2, ph2, N, HH, HH, 1);
    k_check<<<1, 32>>>(ph1, W2, b2, ph2, N, HH, HH, 1, pbad);
    k_sgemm_guard<<<g, 256>>>(ph1, W2, b2, ph2, N, HH, HH, 1, pbad);
  }
  k_conc<<<(N * 32 + 255) / 256, 256>>>(ph2, W3, b3, pconc, N);

  // Dirichlet
  k_gamma<<<(N + 255) / 256, 256>>>(pconc, plg, pmode, N);
  k_finalize<<<B, 256>>>(plg, pconc, out, B, ADIM);
}